// round 1
// baseline (speedup 1.0000x reference)
#include <cuda_runtime.h>
#include <math.h>
#include <stdint.h>

#define B_TOK 8192
#define D_DIM 1024
#define E_NUM 8

// ---------------- scratch (device globals; no allocs allowed) ----------------
__device__ int   g_counts[E_NUM];
__device__ int   g_bucket_tok [E_NUM * B_TOK];   // token id per bucket entry
__device__ int   g_bucket_slot[E_NUM * B_TOK];   // slot = b*2 + k
__device__ float g_gate[B_TOK * 2];              // top-2 softmax gates per token
__device__ float g_partial[(size_t)B_TOK * 2 * D_DIM];  // exp(expert_out) per slot (64 MB)

// ---------------- kernel 0: zero bucket counts ----------------
__global__ void zero_counts_kernel() {
    if (threadIdx.x < E_NUM) g_counts[threadIdx.x] = 0;
}

__device__ __forceinline__ float softplus_stable(float z) {
    // log(1 + exp(z)) = max(z,0) + log1p(exp(-|z|))
    return fmaxf(z, 0.0f) + log1pf(expf(-fabsf(z)));
}

// ---------------- kernel 1: gating (1 warp per token) ----------------
__global__ void gating_kernel(const float* __restrict__ x,
                              const float* __restrict__ noise,
                              const float* __restrict__ w_gate,
                              const float* __restrict__ w_noise) {
    const int warp = threadIdx.x >> 5;
    const int lane = threadIdx.x & 31;
    const int b = blockIdx.x * 8 + warp;
    if (b >= B_TOK) return;

    float accC[8] = {0.f,0.f,0.f,0.f,0.f,0.f,0.f,0.f};
    float accN[8] = {0.f,0.f,0.f,0.f,0.f,0.f,0.f,0.f};
    const float* xr = x + (size_t)b * D_DIM;

    for (int d = lane; d < D_DIM; d += 32) {
        float xv = xr[d];
        const float4* wg = reinterpret_cast<const float4*>(w_gate  + (size_t)d * 8);
        const float4* wn = reinterpret_cast<const float4*>(w_noise + (size_t)d * 8);
        float4 g0 = wg[0], g1 = wg[1];
        float4 n0 = wn[0], n1 = wn[1];
        accC[0] = fmaf(xv, g0.x, accC[0]); accC[1] = fmaf(xv, g0.y, accC[1]);
        accC[2] = fmaf(xv, g0.z, accC[2]); accC[3] = fmaf(xv, g0.w, accC[3]);
        accC[4] = fmaf(xv, g1.x, accC[4]); accC[5] = fmaf(xv, g1.y, accC[5]);
        accC[6] = fmaf(xv, g1.z, accC[6]); accC[7] = fmaf(xv, g1.w, accC[7]);
        accN[0] = fmaf(xv, n0.x, accN[0]); accN[1] = fmaf(xv, n0.y, accN[1]);
        accN[2] = fmaf(xv, n0.z, accN[2]); accN[3] = fmaf(xv, n0.w, accN[3]);
        accN[4] = fmaf(xv, n1.x, accN[4]); accN[5] = fmaf(xv, n1.y, accN[5]);
        accN[6] = fmaf(xv, n1.z, accN[6]); accN[7] = fmaf(xv, n1.w, accN[7]);
    }

    #pragma unroll
    for (int e = 0; e < 8; e++) {
        #pragma unroll
        for (int off = 16; off > 0; off >>= 1) {
            accC[e] += __shfl_xor_sync(0xffffffffu, accC[e], off);
            accN[e] += __shfl_xor_sync(0xffffffffu, accN[e], off);
        }
    }

    if (lane == 0) {
        float logits[8];
        #pragma unroll
        for (int e = 0; e < 8; e++) {
            float sd = softplus_stable(accN[e]) + 0.01f;
            logits[e] = fmaf(noise[(size_t)b * E_NUM + e], sd, accC[e]);
        }
        // top-2, earlier index wins ties (strict >): matches jax.lax.top_k
        int i0 = 0; float v0 = logits[0];
        #pragma unroll
        for (int e = 1; e < 8; e++) { if (logits[e] > v0) { v0 = logits[e]; i0 = e; } }
        int i1 = -1; float v1 = -INFINITY;
        #pragma unroll
        for (int e = 0; e < 8; e++) {
            if (e != i0 && logits[e] > v1) { v1 = logits[e]; i1 = e; }
        }
        // softmax over [v0, v1], v0 >= v1
        float ex = expf(v1 - v0);
        float inv = 1.0f / (1.0f + ex);
        float g0 = inv, g1 = ex * inv;
        g_gate[b * 2 + 0] = g0;
        g_gate[b * 2 + 1] = g1;

        int p0 = atomicAdd(&g_counts[i0], 1);
        g_bucket_tok [i0 * B_TOK + p0] = b;
        g_bucket_slot[i0 * B_TOK + p0] = b * 2 + 0;
        int p1 = atomicAdd(&g_counts[i1], 1);
        g_bucket_tok [i1 * B_TOK + p1] = b;
        g_bucket_slot[i1 * B_TOK + p1] = b * 2 + 1;
    }
}

// ---------------- kernel 2: per-expert gathered GEMM + exp epilogue ----------------
#define BM 64
#define BN 64
#define BK 16

__global__ __launch_bounds__(256)
void expert_gemm_kernel(const float* __restrict__ x,
                        const float* __restrict__ W,     // [E, D, D]
                        const float* __restrict__ bias)  // [E, D]
{
    const int e = blockIdx.z;
    const int count = g_counts[e];
    const int m0 = blockIdx.y * BM;
    if (m0 >= count) return;
    const int n0 = blockIdx.x * BN;

    __shared__ float As[BK][BM + 1];  // [k][m], padded
    __shared__ float Bs[BK][BN];
    __shared__ int   stok [BM];
    __shared__ int   sslot[BM];

    const int tid = threadIdx.x;
    if (tid < BM) {
        int m = m0 + tid;
        bool ok = (m < count);
        stok [tid] = ok ? g_bucket_tok [e * B_TOK + m] : -1;
        sslot[tid] = ok ? g_bucket_slot[e * B_TOK + m] : -1;
    }
    __syncthreads();

    const int tx = tid & 15;   // n-tile index (0..15)
    const int ty = tid >> 4;   // m-tile index (0..15)

    float acc[4][4];
    #pragma unroll
    for (int i = 0; i < 4; i++)
        #pragma unroll
        for (int j = 0; j < 4; j++) acc[i][j] = 0.0f;

    const float* We = W + (size_t)e * D_DIM * D_DIM;

    for (int kt = 0; kt < D_DIM; kt += BK) {
        // A tile: 64 rows x 16 k, gathered rows
        #pragma unroll
        for (int r = 0; r < 4; r++) {
            int linear = r * 256 + tid;
            int k = linear & 15;
            int m = linear >> 4;
            int tok = stok[m];
            As[k][m] = (tok >= 0) ? x[(size_t)tok * D_DIM + kt + k] : 0.0f;
        }
        // B tile: 16 k x 64 n, coalesced
        #pragma unroll
        for (int r = 0; r < 4; r++) {
            int k = (tid >> 6) + r * 4;
            int n = tid & 63;
            Bs[k][n] = We[(size_t)(kt + k) * D_DIM + n0 + n];
        }
        __syncthreads();

        #pragma unroll
        for (int k = 0; k < BK; k++) {
            float a[4], bb[4];
            #pragma unroll
            for (int i = 0; i < 4; i++) a[i]  = As[k][ty * 4 + i];
            #pragma unroll
            for (int j = 0; j < 4; j++) bb[j] = Bs[k][tx * 4 + j];
            #pragma unroll
            for (int i = 0; i < 4; i++)
                #pragma unroll
                for (int j = 0; j < 4; j++)
                    acc[i][j] = fmaf(a[i], bb[j], acc[i][j]);
        }
        __syncthreads();
    }

    // epilogue: p = exp(acc + bias); write to per-slot partial buffer
    #pragma unroll
    for (int i = 0; i < 4; i++) {
        int m = ty * 4 + i;
        int slot = sslot[m];
        if (slot < 0) continue;
        float* prow = g_partial + (size_t)slot * D_DIM + n0;
        #pragma unroll
        for (int j = 0; j < 4; j++) {
            int n = tx * 4 + j;
            float y = acc[i][j] + bias[(size_t)e * D_DIM + n0 + n];
            prow[n] = expf(y);
        }
    }
}

// ---------------- kernel 3: combine (log of gated mixture) ----------------
__global__ void combine_kernel(float* __restrict__ out) {
    int idx = blockIdx.x * 256 + threadIdx.x;
    if (idx >= B_TOK * D_DIM) return;
    int b = idx >> 10;        // / D_DIM
    int h = idx & 1023;       // % D_DIM
    float g0 = g_gate[b * 2 + 0];
    float g1 = g_gate[b * 2 + 1];
    float p0 = g_partial[((size_t)(b * 2 + 0) << 10) + h];
    float p1 = g_partial[((size_t)(b * 2 + 1) << 10) + h];
    float c = fmaf(g0, p0, g1 * p1);
    if (c == 0.0f) c = 2.2204460492503131e-16f;  // float64 eps, per reference
    out[idx] = logf(c);
}

// ---------------- launch ----------------
extern "C" void kernel_launch(void* const* d_in, const int* in_sizes, int n_in,
                              void* d_out, int out_size) {
    const float* x         = (const float*)d_in[0];  // [8192,1024]
    const float* noise     = (const float*)d_in[1];  // [8192,8]
    const float* w_gate    = (const float*)d_in[2];  // [1024,8]
    const float* w_noise   = (const float*)d_in[3];  // [1024,8]
    const float* W_experts = (const float*)d_in[4];  // [8,1024,1024]
    const float* b_experts = (const float*)d_in[5];  // [8,1024]
    float* out = (float*)d_out;

    zero_counts_kernel<<<1, 32>>>();
    gating_kernel<<<B_TOK / 8, 256>>>(x, noise, w_gate, w_noise);

    dim3 ggrid(D_DIM / BN, B_TOK / BM, E_NUM);  // (16, 128, 8); inactive m-tiles exit early
    expert_gemm_kernel<<<ggrid, 256>>>(x, W_experts, b_experts);

    combine_kernel<<<(B_TOK * D_DIM) / 256, 256>>>(out);
}

// round 3
// speedup vs baseline: 2.9465x; 2.9465x over previous
#include <cuda_runtime.h>
#include <cuda_fp16.h>
#include <math.h>
#include <stdint.h>

#define B_TOK 8192
#define D_DIM 1024
#define E_NUM 8

// ---------------- scratch (device globals; no allocs allowed) ----------------
__device__ int    g_counts[E_NUM];
__device__ int    g_bucket_tok [E_NUM * B_TOK];
__device__ int    g_bucket_slot[E_NUM * B_TOK];
__device__ float  g_gate[B_TOK * 2];
__device__ float  g_partial[(size_t)B_TOK * 2 * D_DIM];       // exp(expert_out) per slot
__device__ __half g_xhi[(size_t)B_TOK * D_DIM];
__device__ __half g_xlo[(size_t)B_TOK * D_DIM];
__device__ __half g_whi[(size_t)E_NUM * D_DIM * D_DIM];       // W^T hi, [E][N][K]
__device__ __half g_wlo[(size_t)E_NUM * D_DIM * D_DIM];       // W^T lo, [E][N][K]

// ---------------- PTX helpers (all sm_80-baseline, no arch-specific features) ----
__device__ __forceinline__ uint32_t smem_u32(const void* p) {
    uint32_t a;
    asm("{ .reg .u64 t; cvta.to.shared.u64 t, %1; cvt.u32.u64 %0, t; }" : "=r"(a) : "l"(p));
    return a;
}

#define CP16(dst, src) \
    asm volatile("cp.async.cg.shared.global [%0], [%1], 16;" \
        :: "r"(dst), "l"(__cvta_generic_to_global(src)) : "memory")
#define CP_COMMIT() asm volatile("cp.async.commit_group;" ::: "memory")
#define CP_WAIT1()  asm volatile("cp.async.wait_group 1;" ::: "memory")
#define CP_WAIT0()  asm volatile("cp.async.wait_group 0;" ::: "memory")

#define LDSM4(r, addr) \
    asm volatile("ldmatrix.sync.aligned.m8n8.x4.shared.b16 {%0,%1,%2,%3}, [%4];" \
        : "=r"((r)[0]), "=r"((r)[1]), "=r"((r)[2]), "=r"((r)[3]) : "r"(addr))

#define MMA16816(d, a, b0, b1) \
    asm volatile("mma.sync.aligned.m16n8k16.row.col.f32.f16.f16.f32 " \
        "{%0,%1,%2,%3}, {%4,%5,%6,%7}, {%8,%9}, {%0,%1,%2,%3};" \
        : "+f"((d)[0]), "+f"((d)[1]), "+f"((d)[2]), "+f"((d)[3]) \
        : "r"((a)[0]), "r"((a)[1]), "r"((a)[2]), "r"((a)[3]), "r"(b0), "r"(b1))

#define SWZ(row, chunk) ((uint32_t)((row) * 128 + (((chunk) ^ ((row) & 7)) << 4)))

// ---------------- kernel 0: zero bucket counts ----------------
__global__ void zero_counts_kernel() {
    if (threadIdx.x < E_NUM) g_counts[threadIdx.x] = 0;
}

__device__ __forceinline__ float softplus_stable(float z) {
    return fmaxf(z, 0.0f) + log1pf(expf(-fabsf(z)));
}

// ---------------- kernel 1: gating (1 warp per token) ----------------
__global__ void gating_kernel(const float* __restrict__ x,
                              const float* __restrict__ noise,
                              const float* __restrict__ w_gate,
                              const float* __restrict__ w_noise) {
    const int warp = threadIdx.x >> 5;
    const int lane = threadIdx.x & 31;
    const int b = blockIdx.x * 8 + warp;
    if (b >= B_TOK) return;

    float accC[8] = {0.f,0.f,0.f,0.f,0.f,0.f,0.f,0.f};
    float accN[8] = {0.f,0.f,0.f,0.f,0.f,0.f,0.f,0.f};
    const float* xr = x + (size_t)b * D_DIM;

    for (int d = lane; d < D_DIM; d += 32) {
        float xv = xr[d];
        const float4* wg = reinterpret_cast<const float4*>(w_gate  + (size_t)d * 8);
        const float4* wn = reinterpret_cast<const float4*>(w_noise + (size_t)d * 8);
        float4 g0 = wg[0], g1 = wg[1];
        float4 n0 = wn[0], n1 = wn[1];
        accC[0] = fmaf(xv, g0.x, accC[0]); accC[1] = fmaf(xv, g0.y, accC[1]);
        accC[2] = fmaf(xv, g0.z, accC[2]); accC[3] = fmaf(xv, g0.w, accC[3]);
        accC[4] = fmaf(xv, g1.x, accC[4]); accC[5] = fmaf(xv, g1.y, accC[5]);
        accC[6] = fmaf(xv, g1.z, accC[6]); accC[7] = fmaf(xv, g1.w, accC[7]);
        accN[0] = fmaf(xv, n0.x, accN[0]); accN[1] = fmaf(xv, n0.y, accN[1]);
        accN[2] = fmaf(xv, n0.z, accN[2]); accN[3] = fmaf(xv, n0.w, accN[3]);
        accN[4] = fmaf(xv, n1.x, accN[4]); accN[5] = fmaf(xv, n1.y, accN[5]);
        accN[6] = fmaf(xv, n1.z, accN[6]); accN[7] = fmaf(xv, n1.w, accN[7]);
    }

    #pragma unroll
    for (int e = 0; e < 8; e++) {
        #pragma unroll
        for (int off = 16; off > 0; off >>= 1) {
            accC[e] += __shfl_xor_sync(0xffffffffu, accC[e], off);
            accN[e] += __shfl_xor_sync(0xffffffffu, accN[e], off);
        }
    }

    if (lane == 0) {
        float logits[8];
        #pragma unroll
        for (int e = 0; e < 8; e++) {
            float sd = softplus_stable(accN[e]) + 0.01f;
            logits[e] = fmaf(noise[(size_t)b * E_NUM + e], sd, accC[e]);
        }
        int i0 = 0; float v0 = logits[0];
        #pragma unroll
        for (int e = 1; e < 8; e++) { if (logits[e] > v0) { v0 = logits[e]; i0 = e; } }
        int i1 = -1; float v1 = -INFINITY;
        #pragma unroll
        for (int e = 0; e < 8; e++) {
            if (e != i0 && logits[e] > v1) { v1 = logits[e]; i1 = e; }
        }
        float ex = expf(v1 - v0);
        float inv = 1.0f / (1.0f + ex);
        g_gate[b * 2 + 0] = inv;
        g_gate[b * 2 + 1] = ex * inv;

        int p0 = atomicAdd(&g_counts[i0], 1);
        g_bucket_tok [i0 * B_TOK + p0] = b;
        g_bucket_slot[i0 * B_TOK + p0] = b * 2 + 0;
        int p1 = atomicAdd(&g_counts[i1], 1);
        g_bucket_tok [i1 * B_TOK + p1] = b;
        g_bucket_slot[i1 * B_TOK + p1] = b * 2 + 1;
    }
}

// ---------------- kernel 2a: split x -> fp16 hi/lo ----------------
__global__ __launch_bounds__(256)
void split_x_kernel(const float* __restrict__ x) {
    int idx = blockIdx.x * 256 + threadIdx.x;     // over B*D/4
    float4 v = *(const float4*)(x + (size_t)idx * 4);
    __half h0 = __float2half_rn(v.x), h1 = __float2half_rn(v.y);
    __half h2 = __float2half_rn(v.z), h3 = __float2half_rn(v.w);
    __half l0 = __float2half_rn(v.x - __half2float(h0));
    __half l1 = __float2half_rn(v.y - __half2float(h1));
    __half l2 = __float2half_rn(v.z - __half2float(h2));
    __half l3 = __float2half_rn(v.w - __half2float(h3));
    __half2* dh = (__half2*)(g_xhi + (size_t)idx * 4);
    __half2* dl = (__half2*)(g_xlo + (size_t)idx * 4);
    dh[0] = __halves2half2(h0, h1); dh[1] = __halves2half2(h2, h3);
    dl[0] = __halves2half2(l0, l1); dl[1] = __halves2half2(l2, l3);
}

// ---------------- kernel 2b: transpose + fp16 hi/lo split of W ----------------
// whi/wlo[e][n][k] = split(W[e][k][n])
__global__ __launch_bounds__(256)
void prep_w_kernel(const float* __restrict__ W) {
    __shared__ float tile[32][33];
    const int e  = blockIdx.z;
    const int k0 = blockIdx.y * 32;
    const int n0 = blockIdx.x * 32;
    const int tx = threadIdx.x;        // 0..31
    const int ty = threadIdx.y;        // 0..7
    const float* We = W + (size_t)e * D_DIM * D_DIM;

    #pragma unroll
    for (int i = 0; i < 32; i += 8)
        tile[ty + i][tx] = We[(size_t)(k0 + ty + i) * D_DIM + n0 + tx];
    __syncthreads();

    #pragma unroll
    for (int i = 0; i < 32; i += 8) {
        float v = tile[tx][ty + i];    // = W[k0+tx][n0+ty+i]
        __half hi = __float2half_rn(v);
        __half lo = __float2half_rn(v - __half2float(hi));
        size_t o = ((size_t)(e * D_DIM + n0 + ty + i)) * D_DIM + k0 + tx;
        g_whi[o] = hi;
        g_wlo[o] = lo;
    }
}

// ---------------- kernel 3: routed 3-pass fp16 mma.sync GEMM ----------------
#define BMh 128
#define BNh 128
#define BKh 64                         // halfs per k-chunk = 128 B row (SW128)
#define NCHUNK (D_DIM / BKh)           // 16
#define STG 65536                      // Ahi 16K | Alo 16K | Bhi 16K | Blo 16K
#define OFF_ALO 16384
#define OFF_BHI 32768
#define OFF_BLO 49152
#define SMEM_GEMM (1024 + 2 * STG)

__device__ __forceinline__ void load_stage(uint32_t sbuf, const int* stok,
                                           const __half* __restrict__ wh,
                                           const __half* __restrict__ wl,
                                           int kt, int tid) {
    #pragma unroll
    for (int i = 0; i < 4; i++) {
        int lin = i * 256 + tid;
        int row = lin >> 3, ch = lin & 7;
        int tok = stok[row];
        const __half* sa = g_xhi + (size_t)tok * D_DIM + kt + ch * 8;
        const __half* sl = g_xlo + (size_t)tok * D_DIM + kt + ch * 8;
        uint32_t d = sbuf + SWZ(row, ch);
        CP16(d, sa);
        CP16(d + OFF_ALO, sl);
    }
    #pragma unroll
    for (int i = 0; i < 4; i++) {
        int lin = i * 256 + tid;
        int row = lin >> 3, ch = lin & 7;
        const __half* sb = wh + (size_t)row * D_DIM + kt + ch * 8;
        const __half* sl = wl + (size_t)row * D_DIM + kt + ch * 8;
        uint32_t d = sbuf + OFF_BHI + SWZ(row, ch);
        CP16(d, sb);
        CP16(d + 16384, sl);   // OFF_BLO - OFF_BHI
    }
}

__global__ __launch_bounds__(256, 1)
void expert_hmma_kernel(const float* __restrict__ bias) {
    const int e     = blockIdx.z;
    const int count = g_counts[e];
    const int m0    = blockIdx.y * BMh;
    if (m0 >= count) return;
    const int n0    = blockIdx.x * BNh;

    extern __shared__ char smraw[];
    int* stok  = (int*)smraw;            // [128]
    int* sslot = (int*)(smraw + 512);    // [128]
    const uint32_t sb0 = smem_u32(smraw) + 1024;           // stage 0
    const uint32_t sb1 = sb0 + STG;                        // stage 1

    const int tid  = threadIdx.x;
    const int wid  = tid >> 5;
    const int lane = tid & 31;
    const int wm   = (wid & 3) * 32;     // warp m offset in tile
    const int wn   = (wid >> 2) * 64;    // warp n offset in tile

    if (tid < BMh) {
        int m = m0 + tid;
        bool ok = (m < count);
        stok [tid] = ok ? g_bucket_tok [e * B_TOK + m] : 0;
        sslot[tid] = ok ? g_bucket_slot[e * B_TOK + m] : -1;
    }
    __syncthreads();

    const __half* wh = g_whi + ((size_t)e * D_DIM + n0) * D_DIM;
    const __half* wl = g_wlo + ((size_t)e * D_DIM + n0) * D_DIM;

    float acc[2][8][4];
    #pragma unroll
    for (int mt = 0; mt < 2; mt++)
        #pragma unroll
        for (int nt = 0; nt < 8; nt++)
            #pragma unroll
            for (int c = 0; c < 4; c++) acc[mt][nt][c] = 0.0f;

    load_stage(sb0, stok, wh, wl, 0, tid);
    CP_COMMIT();

    const int lrow = lane & 15;
    const int lsel = lane >> 4;

    for (int c = 0; c < NCHUNK; c++) {
        const uint32_t sbuf = (c & 1) ? sb1 : sb0;
        if (c + 1 < NCHUNK) {
            load_stage((c & 1) ? sb0 : sb1, stok, wh, wl, (c + 1) * BKh, tid);
            CP_COMMIT();
            CP_WAIT1();
        } else {
            CP_WAIT0();
        }
        __syncthreads();

        #pragma unroll
        for (int ks = 0; ks < 4; ks++) {
            const int chunk = ks * 2 + lsel;
            uint32_t ahi[2][4], alo[2][4];
            #pragma unroll
            for (int mt = 0; mt < 2; mt++) {
                int r = wm + mt * 16 + lrow;
                uint32_t ad = sbuf + SWZ(r, chunk);
                LDSM4(ahi[mt], ad);
                LDSM4(alo[mt], ad + OFF_ALO);
            }
            uint32_t bhi[4][4], blo[4][4];
            #pragma unroll
            for (int ng = 0; ng < 4; ng++) {
                int r = wn + ng * 16 + lrow;
                uint32_t bd = sbuf + OFF_BHI + SWZ(r, chunk);
                LDSM4(bhi[ng], bd);
                LDSM4(blo[ng], bd + 16384);
            }
            #pragma unroll
            for (int mt = 0; mt < 2; mt++)
                #pragma unroll
                for (int nt = 0; nt < 8; nt++) {
                    int ng = nt >> 1, o = nt & 1;
                    MMA16816(acc[mt][nt], ahi[mt], bhi[ng][o], bhi[ng][2 + o]);
                    MMA16816(acc[mt][nt], ahi[mt], blo[ng][o], blo[ng][2 + o]);
                    MMA16816(acc[mt][nt], alo[mt], bhi[ng][o], bhi[ng][2 + o]);
                }
        }
        __syncthreads();
    }

    // epilogue: fused bias + exp, scatter to per-slot partials
    #pragma unroll
    for (int mt = 0; mt < 2; mt++) {
        #pragma unroll
        for (int h = 0; h < 2; h++) {
            int m = wm + mt * 16 + (lane >> 2) + h * 8;
            int slot = sslot[m];
            if (slot < 0) continue;
            float* pr = g_partial + ((size_t)slot << 10);
            #pragma unroll
            for (int nt = 0; nt < 8; nt++) {
                int col = n0 + wn + nt * 8 + (lane & 3) * 2;
                float2 bv = *(const float2*)(bias + (size_t)e * D_DIM + col);
                float2 o;
                o.x = expf(acc[mt][nt][h * 2 + 0] + bv.x);
                o.y = expf(acc[mt][nt][h * 2 + 1] + bv.y);
                *(float2*)(pr + col) = o;
            }
        }
    }
}

// ---------------- kernel 4: combine ----------------
__global__ void combine_kernel(float* __restrict__ out) {
    int idx = blockIdx.x * 256 + threadIdx.x;        // over B*D/4
    int b = idx >> 8;
    int h4 = (idx & 255) << 2;
    float g0 = g_gate[b * 2 + 0];
    float g1 = g_gate[b * 2 + 1];
    float4 p0 = *(const float4*)(g_partial + ((size_t)(b * 2 + 0) << 10) + h4);
    float4 p1 = *(const float4*)(g_partial + ((size_t)(b * 2 + 1) << 10) + h4);
    float4 o;
    float c0 = fmaf(g0, p0.x, g1 * p1.x);
    float c1 = fmaf(g0, p0.y, g1 * p1.y);
    float c2 = fmaf(g0, p0.z, g1 * p1.z);
    float c3 = fmaf(g0, p0.w, g1 * p1.w);
    const float EPSF = 2.2204460492503131e-16f;
    o.x = logf(c0 == 0.0f ? EPSF : c0);
    o.y = logf(c1 == 0.0f ? EPSF : c1);
    o.z = logf(c2 == 0.0f ? EPSF : c2);
    o.w = logf(c3 == 0.0f ? EPSF : c3);
    *(float4*)(out + (size_t)b * D_DIM + h4) = o;
}

// ---------------- launch ----------------
extern "C" void kernel_launch(void* const* d_in, const int* in_sizes, int n_in,
                              void* d_out, int out_size) {
    const float* x         = (const float*)d_in[0];  // [8192,1024]
    const float* noise     = (const float*)d_in[1];  // [8192,8]
    const float* w_gate    = (const float*)d_in[2];  // [1024,8]
    const float* w_noise   = (const float*)d_in[3];  // [1024,8]
    const float* W_experts = (const float*)d_in[4];  // [8,1024,1024]
    const float* b_experts = (const float*)d_in[5];  // [8,1024]
    float* out = (float*)d_out;

    cudaFuncSetAttribute(expert_hmma_kernel,
                         cudaFuncAttributeMaxDynamicSharedMemorySize, SMEM_GEMM);

    zero_counts_kernel<<<1, 32>>>();
    gating_kernel<<<B_TOK / 8, 256>>>(x, noise, w_gate, w_noise);

    split_x_kernel<<<(B_TOK * D_DIM / 4) / 256, 256>>>(x);
    dim3 pgrid(D_DIM / 32, D_DIM / 32, E_NUM);
    prep_w_kernel<<<pgrid, dim3(32, 8, 1)>>>(W_experts);

    dim3 ggrid(D_DIM / BNh, B_TOK / BMh, E_NUM);  // (8, 64, 8)
    expert_hmma_kernel<<<ggrid, 256, SMEM_GEMM>>>(b_experts);

    combine_kernel<<<(B_TOK * D_DIM / 4) / 256, 256>>>(out);
}